// round 6
// baseline (speedup 1.0000x reference)
#include <cuda_runtime.h>
#include <math.h>

#define Bsz 1024
#define INd 256
#define Hd  512
#define Pd  128

// ---------------- scratch (no allocations allowed) ----------------
__device__ float g_h0[Bsz * Hd];
__device__ float g_h1[Bsz * Hd];
__device__ float g_q [Bsz * Hd];
__device__ float g_k [Bsz * Hd];
__device__ float g_v [Bsz * Hd];

// ---------------- helpers ----------------
__device__ __forceinline__ float ex2f(float x) {
    float y;
    asm("ex2.approx.f32 %0, %1;" : "=f"(y) : "f"(x));
    return y;
}

// ---------------- GEMM: C[M,N] = A[M,K] @ W[N,K]^T + bias ----------------
// Optional fused epilogue: C = res + gelu_exact(acc + bias)
struct GemmArgs {
    const float* A;
    const float* W[3];
    const float* bias[3];
    const float* res;
    float*       C[3];
    int M, N, K;
};

constexpr int BM = 64, BN = 64, BK = 16;

template <int FUSE_GELU>
__global__ __launch_bounds__(256) void gemm_kernel(GemmArgs g) {
    const int z = blockIdx.z;
    const float* __restrict__ A    = g.A;
    const float* __restrict__ W    = g.W[z];
    const float* __restrict__ bias = g.bias[z];
    float* __restrict__ C          = g.C[z];
    const int N = g.N, K = g.K;

    __shared__ float As[BK][BM + 4];
    __shared__ float Ws[BK][BN + 4];

    const int tid = threadIdx.x;
    const int tx = tid & 15;        // n-dir
    const int ty = tid >> 4;        // m-dir
    const int m0 = blockIdx.y * BM;
    const int n0 = blockIdx.x * BN;

    const int lr = tid >> 2;        // 0..63 : row within tile
    const int lk = (tid & 3) * 4;   // 0,4,8,12 : k offset

    float acc[4][4];
#pragma unroll
    for (int i = 0; i < 4; i++)
#pragma unroll
        for (int j = 0; j < 4; j++) acc[i][j] = 0.f;

    const float* Ap = &A[(m0 + lr) * K + lk];
    const float* Wp = &W[(n0 + lr) * K + lk];

    for (int k0 = 0; k0 < K; k0 += BK) {
        float4 av = *(const float4*)(Ap + k0);
        float4 wv = *(const float4*)(Wp + k0);
        As[lk + 0][lr] = av.x; As[lk + 1][lr] = av.y;
        As[lk + 2][lr] = av.z; As[lk + 3][lr] = av.w;
        Ws[lk + 0][lr] = wv.x; Ws[lk + 1][lr] = wv.y;
        Ws[lk + 2][lr] = wv.z; Ws[lk + 3][lr] = wv.w;
        __syncthreads();
#pragma unroll
        for (int kk = 0; kk < BK; kk++) {
            float4 a4 = *(const float4*)&As[kk][ty * 4];
            float4 b4 = *(const float4*)&Ws[kk][tx * 4];
            float ar[4] = {a4.x, a4.y, a4.z, a4.w};
            float br[4] = {b4.x, b4.y, b4.z, b4.w};
#pragma unroll
            for (int i = 0; i < 4; i++)
#pragma unroll
                for (int j = 0; j < 4; j++)
                    acc[i][j] = fmaf(ar[i], br[j], acc[i][j]);
        }
        __syncthreads();
    }

    const int nc = n0 + tx * 4;
    float4 bv = *(const float4*)&bias[nc];
    float bb[4] = {bv.x, bv.y, bv.z, bv.w};
#pragma unroll
    for (int i = 0; i < 4; i++) {
        const int m = m0 + ty * 4 + i;
        float4 o;
        float* op = &o.x;
#pragma unroll
        for (int j = 0; j < 4; j++) {
            float val = acc[i][j] + bb[j];
            if (FUSE_GELU) {
                float gl = 0.5f * val * (1.0f + erff(val * 0.70710678118654752f));
                val = g.res[m * N + nc + j] + gl;
            }
            op[j] = val;
        }
        *(float4*)&C[m * N + nc] = o;
    }
}

// ---------------- attention: h[b,i] += sum_j softmax_j(q_i k_j) v_j ----------------
__global__ __launch_bounds__(256) void attn_kernel(const float* __restrict__ q,
                                                   const float* __restrict__ k,
                                                   const float* __restrict__ v,
                                                   float* __restrict__ h) {
    const int b = blockIdx.x;
    __shared__ float k2s[Hd];
    __shared__ float vs[Hd];
    __shared__ float redmax[256];
    __shared__ float redmin[256];
    const int tid = threadIdx.x;
    const float LOG2E = 1.4426950408889634f;

    float lmax = -1e30f, lmin = 1e30f;
#pragma unroll
    for (int ii = 0; ii < Hd / 256; ii++) {
        int j = tid + ii * 256;
        float kk = k[b * Hd + j] * LOG2E;   // pre-scale: exp(x) = 2^(x*log2e)
        k2s[j] = kk;
        vs[j]  = v[b * Hd + j];
        lmax = fmaxf(lmax, kk);
        lmin = fminf(lmin, kk);
    }
    redmax[tid] = lmax;
    redmin[tid] = lmin;
    __syncthreads();
    for (int s = 128; s > 0; s >>= 1) {
        if (tid < s) {
            redmax[tid] = fmaxf(redmax[tid], redmax[tid + s]);
            redmin[tid] = fminf(redmin[tid], redmin[tid + s]);
        }
        __syncthreads();
    }
    const float kmax = redmax[0], kmin = redmin[0];

    // two output rows per thread, sharing the broadcast k/v LDS stream
    const float q0 = q[b * Hd + tid];
    const float q1 = q[b * Hd + tid + 256];
    const float m0 = (q0 >= 0.f) ? q0 * kmax : q0 * kmin;  // max_j q*k (log2 domain)
    const float m1 = (q1 >= 0.f) ? q1 * kmax : q1 * kmin;

    float d0 = 0.f, d1 = 0.f, n0 = 0.f, n1 = 0.f;
#pragma unroll 8
    for (int j = 0; j < Hd; j++) {
        float kv = k2s[j];
        float vv = vs[j];
        float e0 = ex2f(fmaf(q0, kv, -m0));
        float e1 = ex2f(fmaf(q1, kv, -m1));
        d0 += e0;
        d1 += e1;
        n0 = fmaf(e0, vv, n0);
        n1 = fmaf(e1, vv, n1);
    }
    h[b * Hd + tid]       += n0 / d0;
    h[b * Hd + tid + 256] += n1 / d1;
}

// ---------------- reg head: out[b] = fea[b,:]·reg_w + reg_b ----------------
__global__ __launch_bounds__(256) void reg_kernel(const float* __restrict__ fea,
                                                  const float* __restrict__ reg_w,
                                                  const float* __restrict__ reg_b,
                                                  float* __restrict__ out) {
    const int warp = (blockIdx.x * blockDim.x + threadIdx.x) >> 5;
    const int lane = threadIdx.x & 31;
    if (warp >= Bsz) return;
    float s = 0.f;
#pragma unroll
    for (int p = lane; p < Pd; p += 32)
        s = fmaf(fea[warp * Pd + p], reg_w[p], s);
#pragma unroll
    for (int o = 16; o; o >>= 1) s += __shfl_xor_sync(0xffffffffu, s, o);
    if (lane == 0) out[warp] = s + reg_b[0];
}

// ---------------- launcher ----------------
extern "C" void kernel_launch(void* const* d_in, const int* in_sizes, int n_in,
                              void* d_out, int out_size) {
    const float* x      = (const float*)d_in[0];
    const float* lin0_w = (const float*)d_in[1];
    const float* lin0_b = (const float*)d_in[2];
    const float* b1_qw = (const float*)d_in[3];  const float* b1_qb = (const float*)d_in[4];
    const float* b1_kw = (const float*)d_in[5];  const float* b1_kb = (const float*)d_in[6];
    const float* b1_vw = (const float*)d_in[7];  const float* b1_vb = (const float*)d_in[8];
    const float* b1_f1w = (const float*)d_in[9]; const float* b1_f1b = (const float*)d_in[10];
    const float* b2_qw = (const float*)d_in[11]; const float* b2_qb = (const float*)d_in[12];
    const float* b2_kw = (const float*)d_in[13]; const float* b2_kb = (const float*)d_in[14];
    const float* b2_vw = (const float*)d_in[15]; const float* b2_vb = (const float*)d_in[16];
    const float* b2_f1w = (const float*)d_in[17]; const float* b2_f1b = (const float*)d_in[18];
    const float* fea_w = (const float*)d_in[19]; const float* fea_b = (const float*)d_in[20];
    const float* reg_w = (const float*)d_in[21]; const float* reg_b = (const float*)d_in[22];

    float* out_scalar = (float*)d_out;           // [B]
    float* out_fea    = (float*)d_out + Bsz;     // [B, P]

    float *h0, *h1, *qb, *kb, *vb;
    cudaGetSymbolAddress((void**)&h0, g_h0);
    cudaGetSymbolAddress((void**)&h1, g_h1);
    cudaGetSymbolAddress((void**)&qb, g_q);
    cudaGetSymbolAddress((void**)&kb, g_k);
    cudaGetSymbolAddress((void**)&vb, g_v);

    const dim3 blk(256);

    // 1) h0 = x @ lin0_w^T + b
    {
        GemmArgs a{};
        a.A = x; a.W[0] = lin0_w; a.bias[0] = lin0_b; a.C[0] = h0;
        a.M = Bsz; a.N = Hd; a.K = INd;
        gemm_kernel<0><<<dim3(Hd / BN, Bsz / BM, 1), blk>>>(a);
    }

    // ---- block 1 (h0 -> h1) ----
    {
        GemmArgs a{};
        a.A = h0;
        a.W[0] = b1_qw; a.W[1] = b1_kw; a.W[2] = b1_vw;
        a.bias[0] = b1_qb; a.bias[1] = b1_kb; a.bias[2] = b1_vb;
        a.C[0] = qb; a.C[1] = kb; a.C[2] = vb;
        a.M = Bsz; a.N = Hd; a.K = Hd;
        gemm_kernel<0><<<dim3(Hd / BN, Bsz / BM, 3), blk>>>(a);
    }
    attn_kernel<<<Bsz, blk>>>(qb, kb, vb, h0);
    {
        GemmArgs a{};
        a.A = h0; a.W[0] = b1_f1w; a.bias[0] = b1_f1b; a.res = h0; a.C[0] = h1;
        a.M = Bsz; a.N = Hd; a.K = Hd;
        gemm_kernel<1><<<dim3(Hd / BN, Bsz / BM, 1), blk>>>(a);
    }

    // ---- block 2 (h1 -> h0) ----
    {
        GemmArgs a{};
        a.A = h1;
        a.W[0] = b2_qw; a.W[1] = b2_kw; a.W[2] = b2_vw;
        a.bias[0] = b2_qb; a.bias[1] = b2_kb; a.bias[2] = b2_vb;
        a.C[0] = qb; a.C[1] = kb; a.C[2] = vb;
        a.M = Bsz; a.N = Hd; a.K = Hd;
        gemm_kernel<0><<<dim3(Hd / BN, Bsz / BM, 3), blk>>>(a);
    }
    attn_kernel<<<Bsz, blk>>>(qb, kb, vb, h1);
    {
        GemmArgs a{};
        a.A = h1; a.W[0] = b2_f1w; a.bias[0] = b2_f1b; a.res = h1; a.C[0] = h0;
        a.M = Bsz; a.N = Hd; a.K = Hd;
        gemm_kernel<1><<<dim3(Hd / BN, Bsz / BM, 1), blk>>>(a);
    }

    // 4) fea = h0 @ fea_w^T + fea_b   (written straight into d_out)
    {
        GemmArgs a{};
        a.A = h0; a.W[0] = fea_w; a.bias[0] = fea_b; a.C[0] = out_fea;
        a.M = Bsz; a.N = Pd; a.K = Hd;
        gemm_kernel<0><<<dim3(Pd / BN, Bsz / BM, 1), blk>>>(a);
    }

    // 5) out[b] = fea[b,:]·reg_w + reg_b
    reg_kernel<<<(Bsz * 32) / 256, blk>>>(out_fea, reg_w, reg_b, out_scalar);
}

// round 7
// speedup vs baseline: 1.1545x; 1.1545x over previous
#include <cuda_runtime.h>
#include <math.h>

#define Bsz 1024
#define INd 256
#define Hd  512
#define Pd  128

// ---------------- scratch (no allocations allowed) ----------------
__device__ float g_h0[Bsz * Hd];
__device__ float g_h1[Bsz * Hd];
__device__ float g_q [Bsz * Hd];   // also reused as fea split-K partials (4*B*P = B*H/... fits: 4*1024*128 = 512K = Bsz*Hd)
__device__ float g_k [Bsz * Hd];
__device__ float g_v [Bsz * Hd];

// ---------------- helpers ----------------
__device__ __forceinline__ float ex2f(float x) {
    float y;
    asm("ex2.approx.f32 %0, %1;" : "=f"(y) : "f"(x));
    return y;
}

// packed fp32x2 FMA (FFMA2): 2 fp32 FMAs per instruction, exact per-lane fp32 fma
#define FMA2(c, a, b) \
    asm("fma.rn.f32x2 %0, %1, %2, %0;" : "+l"(c) : "l"(a), "l"(b))
#define PACK2(d, s) \
    asm("mov.b64 %0, {%1, %1};" : "=l"(d) : "f"(s))
#define UNPACK2(lo, hi, s) \
    asm("mov.b64 {%0, %1}, %2;" : "=f"(lo), "=f"(hi) : "l"(s))

// ---------------- GEMM: C[M,N] = A[M,K] @ W[N,K]^T + bias ----------------
// MODE 0: plain, blockIdx.z selects (W,bias,C) triple
// MODE 1: fused epilogue C = res + gelu_exact(acc + bias)
// MODE 2: split-K by 4, blockIdx.z = k-split, no bias, C -> C + z*M*N
struct GemmArgs {
    const float* A;
    const float* W[3];
    const float* bias[3];
    const float* res;
    float*       C[3];
    int M, N, K;
};

constexpr int BM = 64, BN = 64, BK = 16;

template <int MODE>
__global__ __launch_bounds__(256) void gemm_kernel(GemmArgs g) {
    const int z = blockIdx.z;
    const float* __restrict__ A    = g.A;
    const float* __restrict__ W    = (MODE == 0) ? g.W[z]    : g.W[0];
    const float* __restrict__ bias = (MODE == 0) ? g.bias[z] : g.bias[0];
    float* __restrict__ C          = (MODE == 0) ? g.C[z]    : g.C[0];
    const int N = g.N, K = g.K;
    const int kloc = (MODE == 2) ? (K >> 2) : K;
    const int kbeg = (MODE == 2) ? z * kloc : 0;
    if (MODE == 2) C += z * g.M * N;

    __shared__ float As[2][BK][BM + 4];
    __shared__ float Ws[2][BK][BN + 4];

    const int tid = threadIdx.x;
    const int tx = tid & 15;        // n-dir (4 floats = 2 f32x2 pairs)
    const int ty = tid >> 4;        // m-dir
    const int m0 = blockIdx.y * BM;
    const int n0 = blockIdx.x * BN;

    const int lr = tid >> 2;        // 0..63 : row within tile
    const int lk = (tid & 3) * 4;   // 0,4,8,12 : k offset

    unsigned long long acc[4][2];   // 4 m-rows x 2 f32x2 n-pairs = 4x4 fp32
#pragma unroll
    for (int i = 0; i < 4; i++) { acc[i][0] = 0ULL; acc[i][1] = 0ULL; }

    const float* Ap = &A[(m0 + lr) * K + kbeg + lk];
    const float* Wp = &W[(n0 + lr) * K + kbeg + lk];

    const int nstage = kloc / BK;

    // stage 0: global -> smem
    float4 av = *(const float4*)Ap;
    float4 wv = *(const float4*)Wp;
    As[0][lk + 0][lr] = av.x; As[0][lk + 1][lr] = av.y;
    As[0][lk + 2][lr] = av.z; As[0][lk + 3][lr] = av.w;
    Ws[0][lk + 0][lr] = wv.x; Ws[0][lk + 1][lr] = wv.y;
    Ws[0][lk + 2][lr] = wv.z; Ws[0][lk + 3][lr] = wv.w;
    __syncthreads();

    for (int s = 0; s < nstage; s++) {
        const int buf = s & 1;
        // prefetch next stage's global data into registers (hidden under compute)
        if (s + 1 < nstage) {
            av = *(const float4*)(Ap + (s + 1) * BK);
            wv = *(const float4*)(Wp + (s + 1) * BK);
        }

        const float* sA = &As[buf][0][ty * 4];
        const float* sW = &Ws[buf][0][tx * 4];
        float4     a_cur = *(const float4*)sA;
        ulonglong2 b_cur = *(const ulonglong2*)sW;   // 4 fp32 = 2 f32x2 pairs
#pragma unroll
        for (int kk = 0; kk < BK; kk++) {
            const int kn = (kk + 1 < BK) ? kk + 1 : kk;   // register prefetch, distance 1
            float4     a_nxt = *(const float4*)(sA + kn * (BM + 4));
            ulonglong2 b_nxt = *(const ulonglong2*)(sW + kn * (BN + 4));
            unsigned long long aa0, aa1, aa2, aa3;
            PACK2(aa0, a_cur.x); PACK2(aa1, a_cur.y);
            PACK2(aa2, a_cur.z); PACK2(aa3, a_cur.w);
            FMA2(acc[0][0], aa0, b_cur.x); FMA2(acc[0][1], aa0, b_cur.y);
            FMA2(acc[1][0], aa1, b_cur.x); FMA2(acc[1][1], aa1, b_cur.y);
            FMA2(acc[2][0], aa2, b_cur.x); FMA2(acc[2][1], aa2, b_cur.y);
            FMA2(acc[3][0], aa3, b_cur.x); FMA2(acc[3][1], aa3, b_cur.y);
            a_cur = a_nxt; b_cur = b_nxt;
        }

        if (s + 1 < nstage) {
            const int nb = buf ^ 1;
            As[nb][lk + 0][lr] = av.x; As[nb][lk + 1][lr] = av.y;
            As[nb][lk + 2][lr] = av.z; As[nb][lk + 3][lr] = av.w;
            Ws[nb][lk + 0][lr] = wv.x; Ws[nb][lk + 1][lr] = wv.y;
            Ws[nb][lk + 2][lr] = wv.z; Ws[nb][lk + 3][lr] = wv.w;
            __syncthreads();
        }
    }

    const int nc = n0 + tx * 4;
    float4 bv;
    if (MODE == 2) bv = make_float4(0.f, 0.f, 0.f, 0.f);
    else           bv = *(const float4*)&bias[nc];
#pragma unroll
    for (int i = 0; i < 4; i++) {
        const int m = m0 + ty * 4 + i;
        float4 o;
        UNPACK2(o.x, o.y, acc[i][0]);
        UNPACK2(o.z, o.w, acc[i][1]);
        o.x += bv.x; o.y += bv.y; o.z += bv.z; o.w += bv.w;
        if (MODE == 1) {
            float4 r4 = *(const float4*)&g.res[m * N + nc];
            o.x = r4.x + 0.5f * o.x * (1.0f + erff(o.x * 0.70710678118654752f));
            o.y = r4.y + 0.5f * o.y * (1.0f + erff(o.y * 0.70710678118654752f));
            o.z = r4.z + 0.5f * o.z * (1.0f + erff(o.z * 0.70710678118654752f));
            o.w = r4.w + 0.5f * o.w * (1.0f + erff(o.w * 0.70710678118654752f));
        }
        *(float4*)&C[m * N + nc] = o;
    }
}

// ---------------- attention: h[b,i] += sum_j softmax_j(q_i k_j) v_j ----------------
__global__ __launch_bounds__(256) void attn_kernel(const float* __restrict__ q,
                                                   const float* __restrict__ k,
                                                   const float* __restrict__ v,
                                                   float* __restrict__ h) {
    const int b = blockIdx.x;
    __shared__ float k2s[Hd];
    __shared__ float vs[Hd];
    __shared__ float redmax[256];
    __shared__ float redmin[256];
    const int tid = threadIdx.x;
    const float LOG2E = 1.4426950408889634f;

    float lmax = -1e30f, lmin = 1e30f;
#pragma unroll
    for (int ii = 0; ii < Hd / 256; ii++) {
        int j = tid + ii * 256;
        float kk = k[b * Hd + j] * LOG2E;   // pre-scale: exp(x) = 2^(x*log2e)
        k2s[j] = kk;
        vs[j]  = v[b * Hd + j];
        lmax = fmaxf(lmax, kk);
        lmin = fminf(lmin, kk);
    }
    redmax[tid] = lmax;
    redmin[tid] = lmin;
    __syncthreads();
    for (int s = 128; s > 0; s >>= 1) {
        if (tid < s) {
            redmax[tid] = fmaxf(redmax[tid], redmax[tid + s]);
            redmin[tid] = fminf(redmin[tid], redmin[tid + s]);
        }
        __syncthreads();
    }
    const float kmax = redmax[0], kmin = redmin[0];

    // two output rows per thread, sharing the broadcast k/v LDS stream
    const float q0 = q[b * Hd + tid];
    const float q1 = q[b * Hd + tid + 256];
    const float m0 = (q0 >= 0.f) ? q0 * kmax : q0 * kmin;  // max_j q*k (log2 domain)
    const float m1 = (q1 >= 0.f) ? q1 * kmax : q1 * kmin;

    float d0 = 0.f, d1 = 0.f, n0 = 0.f, n1 = 0.f;
#pragma unroll 8
    for (int j = 0; j < Hd; j++) {
        float kv = k2s[j];
        float vv = vs[j];
        float e0 = ex2f(fmaf(q0, kv, -m0));
        float e1 = ex2f(fmaf(q1, kv, -m1));
        d0 += e0;
        d1 += e1;
        n0 = fmaf(e0, vv, n0);
        n1 = fmaf(e1, vv, n1);
    }
    h[b * Hd + tid]       += n0 / d0;
    h[b * Hd + tid + 256] += n1 / d1;
}

// ---------------- fea split-K reduce + bias + reg head ----------------
// part: [4][B, P] partials; writes fea -> out_fea, out[b] = fea·reg_w + reg_b
__global__ __launch_bounds__(128) void fea_reg_kernel(const float* __restrict__ part,
                                                      const float* __restrict__ fea_b,
                                                      const float* __restrict__ reg_w,
                                                      const float* __restrict__ reg_b,
                                                      float* __restrict__ out_fea,
                                                      float* __restrict__ out_scalar) {
    const int b = blockIdx.x;
    const int p = threadIdx.x;
    const int idx = b * Pd + p;
    float s = part[idx]
            + part[Bsz * Pd + idx]
            + part[2 * Bsz * Pd + idx]
            + part[3 * Bsz * Pd + idx]
            + fea_b[p];
    out_fea[idx] = s;

    float d = s * reg_w[p];
#pragma unroll
    for (int o = 16; o; o >>= 1) d += __shfl_xor_sync(0xffffffffu, d, o);
    __shared__ float ws[4];
    if ((p & 31) == 0) ws[p >> 5] = d;
    __syncthreads();
    if (p == 0) out_scalar[b] = ws[0] + ws[1] + ws[2] + ws[3] + reg_b[0];
}

// ---------------- launcher ----------------
extern "C" void kernel_launch(void* const* d_in, const int* in_sizes, int n_in,
                              void* d_out, int out_size) {
    const float* x      = (const float*)d_in[0];
    const float* lin0_w = (const float*)d_in[1];
    const float* lin0_b = (const float*)d_in[2];
    const float* b1_qw = (const float*)d_in[3];  const float* b1_qb = (const float*)d_in[4];
    const float* b1_kw = (const float*)d_in[5];  const float* b1_kb = (const float*)d_in[6];
    const float* b1_vw = (const float*)d_in[7];  const float* b1_vb = (const float*)d_in[8];
    const float* b1_f1w = (const float*)d_in[9]; const float* b1_f1b = (const float*)d_in[10];
    const float* b2_qw = (const float*)d_in[11]; const float* b2_qb = (const float*)d_in[12];
    const float* b2_kw = (const float*)d_in[13]; const float* b2_kb = (const float*)d_in[14];
    const float* b2_vw = (const float*)d_in[15]; const float* b2_vb = (const float*)d_in[16];
    const float* b2_f1w = (const float*)d_in[17]; const float* b2_f1b = (const float*)d_in[18];
    const float* fea_w = (const float*)d_in[19]; const float* fea_b = (const float*)d_in[20];
    const float* reg_w = (const float*)d_in[21]; const float* reg_b = (const float*)d_in[22];

    float* out_scalar = (float*)d_out;           // [B]
    float* out_fea    = (float*)d_out + Bsz;     // [B, P]

    float *h0, *h1, *qb, *kb, *vb;
    cudaGetSymbolAddress((void**)&h0, g_h0);
    cudaGetSymbolAddress((void**)&h1, g_h1);
    cudaGetSymbolAddress((void**)&qb, g_q);
    cudaGetSymbolAddress((void**)&kb, g_k);
    cudaGetSymbolAddress((void**)&vb, g_v);

    const dim3 blk(256);

    // 1) h0 = x @ lin0_w^T + b
    {
        GemmArgs a{};
        a.A = x; a.W[0] = lin0_w; a.bias[0] = lin0_b; a.C[0] = h0;
        a.M = Bsz; a.N = Hd; a.K = INd;
        gemm_kernel<0><<<dim3(Hd / BN, Bsz / BM, 1), blk>>>(a);
    }

    // ---- block 1 (h0 -> h1) ----
    {
        GemmArgs a{};
        a.A = h0;
        a.W[0] = b1_qw; a.W[1] = b1_kw; a.W[2] = b1_vw;
        a.bias[0] = b1_qb; a.bias[1] = b1_kb; a.bias[2] = b1_vb;
        a.C[0] = qb; a.C[1] = kb; a.C[2] = vb;
        a.M = Bsz; a.N = Hd; a.K = Hd;
        gemm_kernel<0><<<dim3(Hd / BN, Bsz / BM, 3), blk>>>(a);
    }
    attn_kernel<<<Bsz, blk>>>(qb, kb, vb, h0);
    {
        GemmArgs a{};
        a.A = h0; a.W[0] = b1_f1w; a.bias[0] = b1_f1b; a.res = h0; a.C[0] = h1;
        a.M = Bsz; a.N = Hd; a.K = Hd;
        gemm_kernel<1><<<dim3(Hd / BN, Bsz / BM, 1), blk>>>(a);
    }

    // ---- block 2 (h1 -> h0) ----
    {
        GemmArgs a{};
        a.A = h1;
        a.W[0] = b2_qw; a.W[1] = b2_kw; a.W[2] = b2_vw;
        a.bias[0] = b2_qb; a.bias[1] = b2_kb; a.bias[2] = b2_vb;
        a.C[0] = qb; a.C[1] = kb; a.C[2] = vb;
        a.M = Bsz; a.N = Hd; a.K = Hd;
        gemm_kernel<0><<<dim3(Hd / BN, Bsz / BM, 3), blk>>>(a);
    }
    attn_kernel<<<Bsz, blk>>>(qb, kb, vb, h1);
    {
        GemmArgs a{};
        a.A = h1; a.W[0] = b2_f1w; a.bias[0] = b2_f1b; a.res = h1; a.C[0] = h0;
        a.M = Bsz; a.N = Hd; a.K = Hd;
        gemm_kernel<1><<<dim3(Hd / BN, Bsz / BM, 1), blk>>>(a);
    }

    // 4) fea partials: split-K by 4 -> 128 CTAs (scratch g_q is free now)
    {
        GemmArgs a{};
        a.A = h0; a.W[0] = fea_w; a.C[0] = qb;   // partials in g_q
        a.M = Bsz; a.N = Pd; a.K = Hd;
        gemm_kernel<2><<<dim3(Pd / BN, Bsz / BM, 4), blk>>>(a);
    }

    // 5) reduce partials + bias -> fea (d_out), then out[b] = fea·reg_w + reg_b
    fea_reg_kernel<<<Bsz, 128>>>(qb, fea_b, reg_w, reg_b, out_fea, out_scalar);
}